// round 5
// baseline (speedup 1.0000x reference)
#include <cuda_runtime.h>
#include <cuda_fp16.h>

#define XD 128
#define YD 128
#define ZD 8
#define ED 64
#define NITER 3
#define FHD 96
#define FWD 320
#define NPTS (XD*YD*ZD)
#define HW (FHD*FWD)

typedef unsigned long long ull;

__device__ __half g_imgTh[HW * ED];     // (H,W,C) image in fp16, 3.9 MB

__device__ __forceinline__ ull pk2(float x, float y) {
    ull r; asm("mov.b64 %0,{%1,%2};" : "=l"(r) : "f"(x), "f"(y)); return r;
}
__device__ __forceinline__ ull splat(float x) { return pk2(x, x); }
__device__ __forceinline__ void unpk(ull v, float& x, float& y) {
    asm("mov.b64 {%0,%1},%2;" : "=f"(x), "=f"(y) : "l"(v));
}
__device__ __forceinline__ ull fma2(ull a, ull b, ull c) {
    ull d; asm("fma.rn.f32x2 %0,%1,%2,%3;" : "=l"(d) : "l"(a), "l"(b), "l"(c)); return d;
}
__device__ __forceinline__ ull add2(ull a, ull b) {
    ull d; asm("add.rn.f32x2 %0,%1,%2;" : "=l"(d) : "l"(a), "l"(b)); return d;
}

// ---------------------------------------------------------------------------
// Kernel 1: coalesced transpose img (C,H,W) -> (H,W,C) fp16
// ---------------------------------------------------------------------------
__global__ __launch_bounds__(256) void transpose_img_kernel(const float* __restrict__ img) {
    __shared__ float tile[32][65];
    const int r0 = blockIdx.x * 32;
    const int t  = threadIdx.x;
    const int tx = t & 31, ty = t >> 5;
    #pragma unroll
    for (int k = 0; k < 8; ++k) {
        int c = k * 8 + ty;
        tile[tx][c] = img[c * HW + r0 + tx];
    }
    __syncthreads();
    #pragma unroll
    for (int k = 0; k < 8; ++k) {
        int row = k * 4 + (t >> 6);
        int c   = t & 63;
        g_imgTh[(r0 + row) * ED + c] = __float2half(tile[row][c]);
    }
}

// ---------------------------------------------------------------------------
// Kernel 2: fused pipeline. 256 thr = 8 warps; each LANE owns one point.
// smem (floats):
//   sWl[3*4096]=12288 | sWd[3*768]=2304 | per-warp scratch 1424 x 8 = 11392
//   scratch: Gs[32][28]=896 + Fs[8][66]=528 ; Hs[32][34]=1088 overlays Gs
// total 25984 floats = 103936 bytes -> 2 CTAs/SM
// NO CTA-wide sync inside the main loop (weights staged once, read-only).
// ---------------------------------------------------------------------------
__global__ __launch_bounds__(256, 2) void bev_kernel(
    const float* __restrict__ Tv,     const float* __restrict__ intr,
    const float* __restrict__ bev_in,
    const float* __restrict__ W_off,  const float* __restrict__ b_off,
    const float* __restrict__ s_off,  const float* __restrict__ W_w,
    const float* __restrict__ b_w,
    const float* __restrict__ W_l,    const float* __restrict__ b_l,
    const float* __restrict__ ln_g,   const float* __restrict__ ln_b,
    float* __restrict__ out)
{
    extern __shared__ float sm[];
    float* sWl = sm;                   // [3][64][64]
    float* sWd = sm + 12288;           // [3][64][12]
    const int t    = threadIdx.x;
    const int warp = t >> 5;
    const int lane = t & 31;
    float* scr = sm + 12288 + 2304 + warp * 1424;
    float* Gsw = scr;                  // [32][28]  (gather table)
    float* Fsw = scr + 896;            // [8][66]   (transpose buffer)
    float* Hsw = scr;                  // [32][34]  (h stash, overlays Gsw)

    const int p = blockIdx.x * 256 + t;

    // ---- stage ALL weights once ----
    {
        const float4* src = (const float4*)W_l;
        #pragma unroll
        for (int u = 0; u < 12; ++u)
            ((float4*)sWl)[t + u * 256] = src[t + u * 256];
        #pragma unroll
        for (int u = 0; u < 9; ++u) {
            int idx = t + u * 256;
            int i = idx / 768;
            int r = idx - i * 768;
            int e = r / 12, j = r - e * 12;
            float v = 0.0f;
            if (j < 6)      v = W_off[i * 384 + e * 6 + j];
            else if (j < 9) v = W_w[i * 192 + e * 3 + (j - 6)];
            sWd[idx] = v;
        }
    }

    // ---- projected base coords ----
    float pxb, pyb;
    {
        int iz = p & 7;
        int ixy = p >> 3;
        int iy = ixy & 127;
        int ix = ixy >> 7;
        float gx = (float)ix * 0.8f;
        float gy = 51.2f - (float)iy * 0.8f;
        float gz = (float)iz * 0.5f - 2.5f;
        float q0 = Tv[0]*gx + Tv[1]*gy + Tv[2]*gz  + Tv[3];
        float q1 = Tv[4]*gx + Tv[5]*gy + Tv[6]*gz  + Tv[7];
        float q2 = Tv[8]*gx + Tv[9]*gy + Tv[10]*gz + Tv[11];
        float r0 = intr[0]*q0 + intr[1]*q1 + intr[2]*q2;
        float r1 = intr[3]*q0 + intr[4]*q1 + intr[5]*q2;
        float r2 = intr[6]*q0 + intr[7]*q1 + intr[8]*q2;
        float invz = 1.0f / r2;
        float cx = r0 * invz * (1.0f / 640.0f) - 1.0f;
        float cy = r1 * invz * (1.0f / 192.0f) - 1.0f;
        pxb = cx * 160.0f + 159.5f;
        pyb = cy * 48.0f  + 47.5f;
    }

    // ---- load B state into registers via smem transpose (8-row groups) ----
    ull bb[32];
    const int pwarp0 = blockIdx.x * 256 + warp * 32;
    #pragma unroll
    for (int g = 0; g < 4; ++g) {
        #pragma unroll
        for (int q = 0; q < 8; ++q) {
            int pt = pwarp0 + g * 8 + q;
            ull v = *((const ull*)(bev_in + (size_t)pt * ED) + lane);
            *(ull*)&Fsw[q * 66 + 2 * lane] = v;
        }
        __syncwarp();
        if ((lane >> 3) == g) {
            #pragma unroll
            for (int q = 0; q < 32; ++q)
                bb[q] = *(ull*)&Fsw[(lane & 7) * 66 + 2 * q];
        }
        __syncwarp();
    }

    __syncthreads();   // weights staged (only CTA-wide barrier)

    for (int i = 0; i < NITER; ++i) {
        const float* sWl_i = sWl + i * 4096;
        const float* sWd_i = sWd + i * 768;

        // ===== dots: own point, 10 logits, broadcast weight rows =====
        float d[10];
        {
            ull acc[5] = {0, 0, 0, 0, 0};
            #pragma unroll
            for (int ep = 0; ep < 32; ++ep) {
                float be0, be1; unpk(bb[ep], be0, be1);
                ull bs0 = splat(be0), bs1 = splat(be1);
                const ulonglong2* w0 = (const ulonglong2*)&sWd_i[(2 * ep) * 12];
                const ulonglong2* w1 = (const ulonglong2*)&sWd_i[(2 * ep + 1) * 12];
                ulonglong2 wa = w0[0], wb = w0[1], wc = w0[2];
                acc[0] = fma2(bs0, wa.x, acc[0]); acc[1] = fma2(bs0, wa.y, acc[1]);
                acc[2] = fma2(bs0, wb.x, acc[2]); acc[3] = fma2(bs0, wb.y, acc[3]);
                acc[4] = fma2(bs0, wc.x, acc[4]);
                wa = w1[0]; wb = w1[1]; wc = w1[2];
                acc[0] = fma2(bs1, wa.x, acc[0]); acc[1] = fma2(bs1, wa.y, acc[1]);
                acc[2] = fma2(bs1, wb.x, acc[2]); acc[3] = fma2(bs1, wb.y, acc[3]);
                acc[4] = fma2(bs1, wc.x, acc[4]);
            }
            #pragma unroll
            for (int q = 0; q < 5; ++q) unpk(acc[q], d[2 * q], d[2 * q + 1]);
        }

        // ===== G1: offsets/softmax -> per-point gather table =====
        {
            const float sc = __ldg(s_off + i);
            float off[6];
            #pragma unroll
            for (int j = 0; j < 6; ++j) off[j] = (d[j] + __ldg(b_off + i * 6 + j)) * sc;
            float l0 = d[6] + __ldg(b_w + i * 3 + 0);
            float l1 = d[7] + __ldg(b_w + i * 3 + 1);
            float l2 = d[8] + __ldg(b_w + i * 3 + 2);
            float mx = fmaxf(l0, fmaxf(l1, l2));
            float e0 = __expf(l0 - mx), e1 = __expf(l1 - mx), e2 = __expf(l2 - mx);
            float inv = 1.0f / (e0 + e1 + e2);
            float wk[3] = {e0 * inv, e1 * inv, e2 * inv};
            float* grow = Gsw + lane * 28;
            #pragma unroll
            for (int k = 0; k < 3; ++k) {
                float px = fmaf(off[2 * k],     160.0f, pxb);
                float py = fmaf(off[2 * k + 1],  48.0f, pyb);
                float fx = floorf(px), fy = floorf(py);
                int x0 = (int)fx, y0 = (int)fy;
                float wx1 = px - fx, wy1 = py - fy;
                float wx0 = 1.0f - wx1, wy0 = 1.0f - wy1;
                bool vx0 = (unsigned)x0 < (unsigned)FWD, vx1 = (unsigned)(x0 + 1) < (unsigned)FWD;
                bool vy0 = (unsigned)y0 < (unsigned)FHD, vy1 = (unsigned)(y0 + 1) < (unsigned)FHD;
                int xc0 = min(max(x0, 0), FWD - 1), xc1 = min(max(x0 + 1, 0), FWD - 1);
                int yc0 = min(max(y0, 0), FHD - 1), yc1 = min(max(y0 + 1, 0), FHD - 1);
                int rA = yc0 * FWD, rB = yc1 * FWD;
                float W = wk[k];
                float w00 = (vx0 && vy0) ? W * wx0 * wy0 : 0.0f;
                float w01 = (vx1 && vy0) ? W * wx1 * wy0 : 0.0f;
                float w10 = (vx0 && vy1) ? W * wx0 * wy1 : 0.0f;
                float w11 = (vx1 && vy1) ? W * wx1 * wy1 : 0.0f;
                *(float4*)(grow + k * 8) = make_float4(
                    __int_as_float((rA + xc0) << 6), __int_as_float((rA + xc1) << 6),
                    __int_as_float((rB + xc0) << 6), __int_as_float((rB + xc1) << 6));
                *(float4*)(grow + k * 8 + 4) = make_float4(w00, w01, w10, w11);
            }
        }
        __syncwarp();

        // ===== G2: warp-per-point gather, groups of 8, fold into bb =====
        #pragma unroll 1
        for (int g = 0; g < 4; ++g) {
            #pragma unroll 2
            for (int q = 0; q < 8; ++q) {
                const float* grow = Gsw + (g * 8 + q) * 28;
                float a0 = 0.0f, a1 = 0.0f;
                #pragma unroll
                for (int k = 0; k < 3; ++k) {
                    float4 A  = *(const float4*)(grow + k * 8);
                    float4 Wt = *(const float4*)(grow + k * 8 + 4);
                    float2 v;
                    v = __half22float2(*(const __half2*)(g_imgTh + __float_as_int(A.x) + 2 * lane));
                    a0 = fmaf(Wt.x, v.x, a0); a1 = fmaf(Wt.x, v.y, a1);
                    v = __half22float2(*(const __half2*)(g_imgTh + __float_as_int(A.y) + 2 * lane));
                    a0 = fmaf(Wt.y, v.x, a0); a1 = fmaf(Wt.y, v.y, a1);
                    v = __half22float2(*(const __half2*)(g_imgTh + __float_as_int(A.z) + 2 * lane));
                    a0 = fmaf(Wt.z, v.x, a0); a1 = fmaf(Wt.z, v.y, a1);
                    v = __half22float2(*(const __half2*)(g_imgTh + __float_as_int(A.w) + 2 * lane));
                    a0 = fmaf(Wt.w, v.x, a0); a1 = fmaf(Wt.w, v.y, a1);
                }
                *(ull*)&Fsw[q * 66 + 2 * lane] = pk2(a0, a1);
            }
            __syncwarp();
            if ((lane >> 3) == g) {
                #pragma unroll
                for (int q = 0; q < 32; ++q)
                    bb[q] = add2(bb[q], *(ull*)&Fsw[(lane & 7) * 66 + 2 * q]);
            }
            __syncwarp();
        }

        // ===== matvec 64x64 (two halves) + LayerNorm residual =====
        float s1 = 0.0f, s2 = 0.0f;
        ull h[16];
        {
            #pragma unroll
            for (int q = 0; q < 8; ++q) {
                ulonglong2 bl = __ldg((const ulonglong2*)(b_l + i * ED) + q);
                h[2 * q] = bl.x; h[2 * q + 1] = bl.y;
            }
            #pragma unroll
            for (int ep = 0; ep < 32; ++ep) {
                float be0, be1; unpk(bb[ep], be0, be1);
                ull bs0 = splat(be0), bs1 = splat(be1);
                const float* w0 = &sWl_i[(2 * ep) * ED];
                const float* w1 = w0 + ED;
                #pragma unroll
                for (int q = 0; q < 8; ++q) {
                    ulonglong2 a = *(const ulonglong2*)(w0 + 4 * q);
                    h[2 * q]     = fma2(bs0, a.x, h[2 * q]);
                    h[2 * q + 1] = fma2(bs0, a.y, h[2 * q + 1]);
                    ulonglong2 b = *(const ulonglong2*)(w1 + 4 * q);
                    h[2 * q]     = fma2(bs1, b.x, h[2 * q]);
                    h[2 * q + 1] = fma2(bs1, b.y, h[2 * q + 1]);
                }
            }
            #pragma unroll
            for (int q = 0; q < 16; ++q) {
                float a, b; unpk(h[q], a, b);
                s1 += a + b;
                s2 = fmaf(a, a, s2); s2 = fmaf(b, b, s2);
                *(ull*)&Hsw[lane * 34 + 2 * q] = h[q];
            }
        }
        {
            #pragma unroll
            for (int q = 0; q < 8; ++q) {
                ulonglong2 bl = __ldg((const ulonglong2*)(b_l + i * ED + 32) + q);
                h[2 * q] = bl.x; h[2 * q + 1] = bl.y;
            }
            #pragma unroll
            for (int ep = 0; ep < 32; ++ep) {
                float be0, be1; unpk(bb[ep], be0, be1);
                ull bs0 = splat(be0), bs1 = splat(be1);
                const float* w0 = &sWl_i[(2 * ep) * ED + 32];
                const float* w1 = w0 + ED;
                #pragma unroll
                for (int q = 0; q < 8; ++q) {
                    ulonglong2 a = *(const ulonglong2*)(w0 + 4 * q);
                    h[2 * q]     = fma2(bs0, a.x, h[2 * q]);
                    h[2 * q + 1] = fma2(bs0, a.y, h[2 * q + 1]);
                    ulonglong2 b = *(const ulonglong2*)(w1 + 4 * q);
                    h[2 * q]     = fma2(bs1, b.x, h[2 * q]);
                    h[2 * q + 1] = fma2(bs1, b.y, h[2 * q + 1]);
                }
            }
            #pragma unroll
            for (int q = 0; q < 16; ++q) {
                float a, b; unpk(h[q], a, b);
                s1 += a + b;
                s2 = fmaf(a, a, s2); s2 = fmaf(b, b, s2);
            }
        }
        {
            float mu  = s1 * (1.0f / ED);
            float var = s2 * (1.0f / ED) - mu * mu;
            float rstd = rsqrtf(var + 1e-5f);
            #pragma unroll
            for (int q = 0; q < 16; ++q) {
                float a, b; unpk(*(ull*)&Hsw[lane * 34 + 2 * q], a, b);
                float2 g2 = __ldg((const float2*)(ln_g + i * ED) + q);
                float2 e2 = __ldg((const float2*)(ln_b + i * ED) + q);
                float r0 = fmaf((a - mu) * rstd, g2.x, e2.x);
                float r1 = fmaf((b - mu) * rstd, g2.y, e2.y);
                bb[q] = add2(bb[q], pk2(r0, r1));
            }
            #pragma unroll
            for (int q = 0; q < 16; ++q) {
                float a, b; unpk(h[q], a, b);
                float2 g2 = __ldg((const float2*)(ln_g + i * ED + 32) + q);
                float2 e2 = __ldg((const float2*)(ln_b + i * ED + 32) + q);
                float r0 = fmaf((a - mu) * rstd, g2.x, e2.x);
                float r1 = fmaf((b - mu) * rstd, g2.y, e2.y);
                bb[16 + q] = add2(bb[16 + q], pk2(r0, r1));
            }
        }
        __syncwarp();
    }

    // ===== epilogue: z-mean over 8-lane groups =====
    {
        int cell = p >> 3;
        int iy = cell & 127;
        int ix = cell >> 7;
        int cidx = iy * XD + ix;
        bool writer = (lane & 7) == 0;
        #pragma unroll
        for (int q = 0; q < 32; ++q) {
            float a, b; unpk(bb[q], a, b);
            #pragma unroll
            for (int o = 1; o < 8; o <<= 1) {
                a += __shfl_xor_sync(0xffffffffu, a, o);
                b += __shfl_xor_sync(0xffffffffu, b, o);
            }
            if (writer) {
                out[(2 * q)     * (XD * YD) + cidx] = a * 0.125f;
                out[(2 * q + 1) * (XD * YD) + cidx] = b * 0.125f;
            }
        }
    }
}

// ---------------------------------------------------------------------------
extern "C" void kernel_launch(void* const* d_in, const int* in_sizes, int n_in,
                              void* d_out, int out_size) {
    const float* Tv     = (const float*)d_in[0];
    const float* intr   = (const float*)d_in[1];
    const float* img    = (const float*)d_in[2];
    const float* bev_in = (const float*)d_in[3];
    const float* W_off  = (const float*)d_in[4];
    const float* b_off  = (const float*)d_in[5];
    const float* s_off  = (const float*)d_in[6];
    const float* W_w    = (const float*)d_in[7];
    const float* b_w    = (const float*)d_in[8];
    const float* W_l    = (const float*)d_in[9];
    const float* b_l    = (const float*)d_in[10];
    const float* ln_g   = (const float*)d_in[11];
    const float* ln_b   = (const float*)d_in[12];
    float* out = (float*)d_out;

    const int SMEM = 25984 * 4;
    cudaFuncSetAttribute(bev_kernel, cudaFuncAttributeMaxDynamicSharedMemorySize, SMEM);

    transpose_img_kernel<<<HW / 32, 256>>>(img);
    bev_kernel<<<NPTS / 256, 256, SMEM>>>(Tv, intr, bev_in,
                                          W_off, b_off, s_off, W_w, b_w,
                                          W_l, b_l, ln_g, ln_b, out);
}

// round 7
// speedup vs baseline: 1.3174x; 1.3174x over previous
#include <cuda_runtime.h>
#include <cuda_fp16.h>
#include <cstdint>

#define XD 128
#define YD 128
#define ZD 8
#define ED 64
#define NITER 3
#define FHD 96
#define FWD 320
#define NPTS (XD*YD*ZD)
#define HW (FHD*FWD)

typedef unsigned long long ull;

__device__ float g_imgT[HW * ED];   // (H,W,C) fp32 image, 7.9 MB

__device__ __forceinline__ ull pk2(float x, float y) {
    ull r; asm("mov.b64 %0,{%1,%2};" : "=l"(r) : "f"(x), "f"(y)); return r;
}
__device__ __forceinline__ ull splat(float x) { return pk2(x, x); }
__device__ __forceinline__ void unpk(ull v, float& x, float& y) {
    asm("mov.b64 {%0,%1},%2;" : "=f"(x), "=f"(y) : "l"(v));
}
__device__ __forceinline__ ull fma2(ull a, ull b, ull c) {
    ull d; asm("fma.rn.f32x2 %0,%1,%2,%3;" : "=l"(d) : "l"(a), "l"(b), "l"(c)); return d;
}
__device__ __forceinline__ ull add2(ull a, ull b) {
    ull d; asm("add.rn.f32x2 %0,%1,%2;" : "=l"(d) : "l"(a), "l"(b)); return d;
}
__device__ __forceinline__ uint32_t smem_u32(const void* p) {
    uint32_t a; asm("{ .reg .u64 t; cvta.to.shared.u64 t, %1; cvt.u32.u64 %0, t; }" : "=r"(a) : "l"(p));
    return a;
}

#define SWZ(off) ((off) ^ (((off) >> 3) & 0x70))

__device__ __forceinline__ void ldsm_x4(uint32_t& r0, uint32_t& r1, uint32_t& r2, uint32_t& r3,
                                        uint32_t addr) {
    asm volatile("ldmatrix.sync.aligned.m8n8.x4.shared.b16 {%0,%1,%2,%3}, [%4];"
                 : "=r"(r0), "=r"(r1), "=r"(r2), "=r"(r3) : "r"(addr));
}
__device__ __forceinline__ void ldsm_x4t(uint32_t& r0, uint32_t& r1, uint32_t& r2, uint32_t& r3,
                                         uint32_t addr) {
    asm volatile("ldmatrix.sync.aligned.m8n8.x4.trans.shared.b16 {%0,%1,%2,%3}, [%4];"
                 : "=r"(r0), "=r"(r1), "=r"(r2), "=r"(r3) : "r"(addr));
}
__device__ __forceinline__ void mma16816(float& d0, float& d1, float& d2, float& d3,
                                         uint32_t a0, uint32_t a1, uint32_t a2, uint32_t a3,
                                         uint32_t b0, uint32_t b1) {
    asm volatile("mma.sync.aligned.m16n8k16.row.col.f32.f16.f16.f32 "
                 "{%0,%1,%2,%3}, {%4,%5,%6,%7}, {%8,%9}, {%0,%1,%2,%3};"
                 : "+f"(d0), "+f"(d1), "+f"(d2), "+f"(d3)
                 : "r"(a0), "r"(a1), "r"(a2), "r"(a3), "r"(b0), "r"(b1));
}

// smem byte layout
#define SM_AS    0        // 8 warps x 4096B fp16 A tiles [32 rows][64 ch]
#define SM_WB    32768    // 3 x 8192B fp16 W_l tiles (rows e, cols c, SW128)
#define SM_WD    57344    // 3 x 768 floats packed dot weights
#define SM_LN    66560    // 3 x 192 floats: b_l | ln_g | ln_b
#define SM_GS    68864    // 8 warps x 768 floats gather table [32][24]
#define SM_FS    93440    // 8 warps x 528 floats transpose buffer [8][66]
#define SM_TOTAL 110336

// ---------------------------------------------------------------------------
__global__ __launch_bounds__(256) void transpose_img_kernel(const float* __restrict__ img) {
    __shared__ float tile[32][65];
    const int r0 = blockIdx.x * 32;
    const int t  = threadIdx.x;
    const int tx = t & 31, ty = t >> 5;
    #pragma unroll
    for (int k = 0; k < 8; ++k) {
        int c = k * 8 + ty;
        tile[tx][c] = img[c * HW + r0 + tx];
    }
    __syncthreads();
    #pragma unroll
    for (int k = 0; k < 8; ++k) {
        int row = k * 4 + (t >> 6);
        int c   = t & 63;
        g_imgT[(r0 + row) * ED + c] = tile[row][c];
    }
}

// ---------------------------------------------------------------------------
__global__ __launch_bounds__(256, 2) void bev_kernel(
    const float* __restrict__ Tv,     const float* __restrict__ intr,
    const float* __restrict__ bev_in,
    const float* __restrict__ W_off,  const float* __restrict__ b_off,
    const float* __restrict__ s_off,  const float* __restrict__ W_w,
    const float* __restrict__ b_w,
    const float* __restrict__ W_l,    const float* __restrict__ b_l,
    const float* __restrict__ ln_g,   const float* __restrict__ ln_b,
    float* __restrict__ out)
{
    extern __shared__ char smem[];
    const uint32_t smb = smem_u32(smem);
    float* sWd = (float*)(smem + SM_WD);
    float* sLN = (float*)(smem + SM_LN);
    const int t    = threadIdx.x;
    const int warp = t >> 5;
    const int lane = t & 31;
    float* Gsw = (float*)(smem + SM_GS) + warp * 768;   // [32][24]
    float* Fsw = (float*)(smem + SM_FS) + warp * 528;   // [8][66]
    const uint32_t asw = smb + SM_AS + warp * 4096;     // own warp's A tile

    const int p = blockIdx.x * 256 + t;

    // ---- stage W_l as fp16 SW128 tiles (rows e, 128B rows) ----
    for (int idx = t; idx < NITER * 4096; idx += 256) {
        int i = idx >> 12;
        int r = idx & 4095;
        int e = r >> 6, c = r & 63;
        *(__half*)(smem + SM_WB + i * 8192 + SWZ((uint32_t)(e * 128 + c * 2))) =
            __float2half(W_l[idx]);
    }
    // ---- stage packed dot weights ----
    #pragma unroll
    for (int u = 0; u < 9; ++u) {
        int idx = t + u * 256;
        int i = idx / 768;
        int r = idx - i * 768;
        int e = r / 12, j = r - e * 12;
        float v = 0.0f;
        if (j < 6)      v = W_off[i * 384 + e * 6 + j];
        else if (j < 9) v = W_w[i * 192 + e * 3 + (j - 6)];
        sWd[idx] = v;
    }
    // ---- stage LN params: [i][ b_l(64) | ln_g(64) | ln_b(64) ] ----
    for (int idx = t; idx < NITER * 192; idx += 256) {
        int i = idx / 192;
        int r = idx - i * 192;
        int j = r >> 6, e = r & 63;
        float v = (j == 0) ? b_l[i * ED + e] : (j == 1) ? ln_g[i * ED + e] : ln_b[i * ED + e];
        sLN[idx] = v;
    }

    // ---- projected base coords ----
    float pxb, pyb;
    {
        int iz = p & 7;
        int ixy = p >> 3;
        int iy = ixy & 127;
        int ix = ixy >> 7;
        float gx = (float)ix * 0.8f;
        float gy = 51.2f - (float)iy * 0.8f;
        float gz = (float)iz * 0.5f - 2.5f;
        float q0 = Tv[0]*gx + Tv[1]*gy + Tv[2]*gz  + Tv[3];
        float q1 = Tv[4]*gx + Tv[5]*gy + Tv[6]*gz  + Tv[7];
        float q2 = Tv[8]*gx + Tv[9]*gy + Tv[10]*gz + Tv[11];
        float r0 = intr[0]*q0 + intr[1]*q1 + intr[2]*q2;
        float r1 = intr[3]*q0 + intr[4]*q1 + intr[5]*q2;
        float r2 = intr[6]*q0 + intr[7]*q1 + intr[8]*q2;
        float invz = 1.0f / r2;
        float cx = r0 * invz * (1.0f / 640.0f) - 1.0f;
        float cy = r1 * invz * (1.0f / 192.0f) - 1.0f;
        pxb = cx * 160.0f + 159.5f;
        pyb = cy * 48.0f  + 47.5f;
    }

    // ---- load B state into registers (smem transpose, 8-row groups) ----
    ull bb[32];
    const int pwarp0 = blockIdx.x * 256 + warp * 32;
    #pragma unroll
    for (int g = 0; g < 4; ++g) {
        #pragma unroll
        for (int q = 0; q < 8; ++q) {
            int pt = pwarp0 + g * 8 + q;
            ull v = *((const ull*)(bev_in + (size_t)pt * ED) + lane);
            *(ull*)&Fsw[q * 66 + 2 * lane] = v;
        }
        __syncwarp();
        if ((lane >> 3) == g) {
            #pragma unroll
            for (int q = 0; q < 32; ++q)
                bb[q] = *(ull*)&Fsw[(lane & 7) * 66 + 2 * q];
        }
        __syncwarp();
    }

    __syncthreads();   // weights staged

    for (int i = 0; i < NITER; ++i) {
        const float* sWd_i = sWd + i * 768;
        const float* sLN_i = sLN + i * 192;
        const uint32_t wb_i = smb + SM_WB + i * 8192;

        // ===== dots: 10 logits, broadcast weight rows =====
        float d[10];
        {
            ull acc[5] = {0, 0, 0, 0, 0};
            #pragma unroll
            for (int ep = 0; ep < 32; ++ep) {
                float be0, be1; unpk(bb[ep], be0, be1);
                ull bs0 = splat(be0), bs1 = splat(be1);
                const ulonglong2* w0 = (const ulonglong2*)&sWd_i[(2 * ep) * 12];
                const ulonglong2* w1 = (const ulonglong2*)&sWd_i[(2 * ep + 1) * 12];
                ulonglong2 wa = w0[0], wb = w0[1], wc = w0[2];
                acc[0] = fma2(bs0, wa.x, acc[0]); acc[1] = fma2(bs0, wa.y, acc[1]);
                acc[2] = fma2(bs0, wb.x, acc[2]); acc[3] = fma2(bs0, wb.y, acc[3]);
                acc[4] = fma2(bs0, wc.x, acc[4]);
                wa = w1[0]; wb = w1[1]; wc = w1[2];
                acc[0] = fma2(bs1, wa.x, acc[0]); acc[1] = fma2(bs1, wa.y, acc[1]);
                acc[2] = fma2(bs1, wb.x, acc[2]); acc[3] = fma2(bs1, wb.y, acc[3]);
                acc[4] = fma2(bs1, wc.x, acc[4]);
            }
            #pragma unroll
            for (int q = 0; q < 5; ++q) unpk(acc[q], d[2 * q], d[2 * q + 1]);
        }

        // ===== G1: offsets/softmax -> gather table [32][24] =====
        {
            const float sc = __ldg(s_off + i);
            float off[6];
            #pragma unroll
            for (int j = 0; j < 6; ++j) off[j] = (d[j] + __ldg(b_off + i * 6 + j)) * sc;
            float l0 = d[6] + __ldg(b_w + i * 3 + 0);
            float l1 = d[7] + __ldg(b_w + i * 3 + 1);
            float l2 = d[8] + __ldg(b_w + i * 3 + 2);
            float mx = fmaxf(l0, fmaxf(l1, l2));
            float e0 = __expf(l0 - mx), e1 = __expf(l1 - mx), e2 = __expf(l2 - mx);
            float inv = 1.0f / (e0 + e1 + e2);
            float wk[3] = {e0 * inv, e1 * inv, e2 * inv};
            float* grow = Gsw + lane * 24;
            #pragma unroll
            for (int k = 0; k < 3; ++k) {
                float px = fmaf(off[2 * k],     160.0f, pxb);
                float py = fmaf(off[2 * k + 1],  48.0f, pyb);
                float fx = floorf(px), fy = floorf(py);
                int x0 = (int)fx, y0 = (int)fy;
                float wx1 = px - fx, wy1 = py - fy;
                float wx0 = 1.0f - wx1, wy0 = 1.0f - wy1;
                bool vx0 = (unsigned)x0 < (unsigned)FWD, vx1 = (unsigned)(x0 + 1) < (unsigned)FWD;
                bool vy0 = (unsigned)y0 < (unsigned)FHD, vy1 = (unsigned)(y0 + 1) < (unsigned)FHD;
                int xc0 = min(max(x0, 0), FWD - 1), xc1 = min(max(x0 + 1, 0), FWD - 1);
                int yc0 = min(max(y0, 0), FHD - 1), yc1 = min(max(y0 + 1, 0), FHD - 1);
                int rA = yc0 * FWD, rB = yc1 * FWD;
                float W = wk[k];
                float w00 = (vx0 && vy0) ? W * wx0 * wy0 : 0.0f;
                float w01 = (vx1 && vy0) ? W * wx1 * wy0 : 0.0f;
                float w10 = (vx0 && vy1) ? W * wx0 * wy1 : 0.0f;
                float w11 = (vx1 && vy1) ? W * wx1 * wy1 : 0.0f;
                *(float4*)(grow + k * 8) = make_float4(
                    __int_as_float((rA + xc0) << 6), __int_as_float((rA + xc1) << 6),
                    __int_as_float((rB + xc0) << 6), __int_as_float((rB + xc1) << 6));
                *(float4*)(grow + k * 8 + 4) = make_float4(w00, w01, w10, w11);
            }
        }
        __syncwarp();

        // ===== G2: warp-per-point gather (fp32 image), fold into bb =====
        #pragma unroll 1
        for (int g = 0; g < 4; ++g) {
            #pragma unroll 2
            for (int q = 0; q < 8; ++q) {
                const float* grow = Gsw + (g * 8 + q) * 24;
                float a0 = 0.0f, a1 = 0.0f;
                #pragma unroll
                for (int k = 0; k < 3; ++k) {
                    float4 A  = *(const float4*)(grow + k * 8);
                    float4 Wt = *(const float4*)(grow + k * 8 + 4);
                    float2 v;
                    v = *(const float2*)(g_imgT + __float_as_int(A.x) + 2 * lane);
                    a0 = fmaf(Wt.x, v.x, a0); a1 = fmaf(Wt.x, v.y, a1);
                    v = *(const float2*)(g_imgT + __float_as_int(A.y) + 2 * lane);
                    a0 = fmaf(Wt.y, v.x, a0); a1 = fmaf(Wt.y, v.y, a1);
                    v = *(const float2*)(g_imgT + __float_as_int(A.z) + 2 * lane);
                    a0 = fmaf(Wt.z, v.x, a0); a1 = fmaf(Wt.z, v.y, a1);
                    v = *(const float2*)(g_imgT + __float_as_int(A.w) + 2 * lane);
                    a0 = fmaf(Wt.w, v.x, a0); a1 = fmaf(Wt.w, v.y, a1);
                }
                *(ull*)&Fsw[q * 66 + 2 * lane] = pk2(a0, a1);
            }
            __syncwarp();
            if ((lane >> 3) == g) {
                #pragma unroll
                for (int q = 0; q < 32; ++q)
                    bb[q] = add2(bb[q], *(ull*)&Fsw[(lane & 7) * 66 + 2 * q]);
            }
            __syncwarp();
        }

        // ===== write own row of A tile (fp16, SW128) =====
        {
            uint32_t av[32];
            #pragma unroll
            for (int q = 0; q < 32; ++q) {
                float a, b; unpk(bb[q], a, b);
                __half2 hh = __floats2half2_rn(a, b);
                av[q] = *(uint32_t*)&hh;
            }
            #pragma unroll
            for (int cb = 0; cb < 8; ++cb) {
                uint32_t off = SWZ((uint32_t)(lane * 128 + cb * 16));
                *(uint4*)(smem + SM_AS + warp * 4096 + off) =
                    make_uint4(av[4*cb], av[4*cb+1], av[4*cb+2], av[4*cb+3]);
            }
        }
        __syncwarp();

        // ===== matvec via mma.sync, two m16 halves =====
        const int qr = lane >> 2;        // quad row 0..7
        const int qc = (lane & 3) * 2;   // col pair base within n8 tile
        #pragma unroll
        for (int mt = 0; mt < 2; ++mt) {
            // D init with bias b_l
            float D[8][4];
            #pragma unroll
            for (int nt = 0; nt < 8; ++nt) {
                float2 bv = *(const float2*)&sLN_i[nt * 8 + qc];
                D[nt][0] = bv.x; D[nt][1] = bv.y;
                D[nt][2] = bv.x; D[nt][3] = bv.y;
            }
            // lane-pattern addresses
            const uint32_t arow = (uint32_t)(mt * 16 + (lane & 15));
            const uint32_t koff8 = (uint32_t)(((lane >> 4) & 1) << 3);
            #pragma unroll
            for (int kt = 0; kt < 4; ++kt) {
                uint32_t a0, a1, a2, a3;
                ldsm_x4(a0, a1, a2, a3,
                        asw + SWZ(arow * 128 + (kt * 16 + koff8) * 2));
                const uint32_t brow = (uint32_t)(kt * 16 + (lane & 15));
                #pragma unroll
                for (int np = 0; np < 4; ++np) {
                    uint32_t b0, b1, b2, b3;
                    ldsm_x4t(b0, b1, b2, b3,
                             wb_i + SWZ(brow * 128 + (np * 16 + koff8) * 2));
                    mma16816(D[2*np][0],   D[2*np][1],   D[2*np][2],   D[2*np][3],
                             a0, a1, a2, a3, b0, b1);
                    mma16816(D[2*np+1][0], D[2*np+1][1], D[2*np+1][2], D[2*np+1][3],
                             a0, a1, a2, a3, b2, b3);
                }
            }
            // LN stats: rows mt*16+qr and mt*16+qr+8
            float s1a = 0.f, s2a = 0.f, s1b = 0.f, s2b = 0.f;
            #pragma unroll
            for (int nt = 0; nt < 8; ++nt) {
                s1a += D[nt][0] + D[nt][1];
                s2a = fmaf(D[nt][0], D[nt][0], s2a); s2a = fmaf(D[nt][1], D[nt][1], s2a);
                s1b += D[nt][2] + D[nt][3];
                s2b = fmaf(D[nt][2], D[nt][2], s2b); s2b = fmaf(D[nt][3], D[nt][3], s2b);
            }
            #pragma unroll
            for (int o = 1; o < 4; o <<= 1) {
                s1a += __shfl_xor_sync(0xffffffffu, s1a, o);
                s2a += __shfl_xor_sync(0xffffffffu, s2a, o);
                s1b += __shfl_xor_sync(0xffffffffu, s1b, o);
                s2b += __shfl_xor_sync(0xffffffffu, s2b, o);
            }
            float muA = s1a * (1.0f / ED);
            float rsA = rsqrtf(s2a * (1.0f / ED) - muA * muA + 1e-5f);
            float muB = s1b * (1.0f / ED);
            float rsB = rsqrtf(s2b * (1.0f / ED) - muB * muB + 1e-5f);

            // subpass A: rows mt*16 + 0..7 (d0,d1)
            #pragma unroll
            for (int nt = 0; nt < 8; ++nt) {
                int c = nt * 8 + qc;
                float2 gv = *(const float2*)&sLN_i[64 + c];
                float2 bv = *(const float2*)&sLN_i[128 + c];
                float r0 = fmaf((D[nt][0] - muA) * rsA, gv.x, bv.x);
                float r1 = fmaf((D[nt][1] - muA) * rsA, gv.y, bv.y);
                *(float2*)&Fsw[qr * 66 + c] = make_float2(r0, r1);
            }
            __syncwarp();
            if ((lane >> 3) == mt * 2) {
                #pragma unroll
                for (int q = 0; q < 32; ++q)
                    bb[q] = add2(bb[q], *(ull*)&Fsw[(lane & 7) * 66 + 2 * q]);
            }
            __syncwarp();
            // subpass B: rows mt*16 + 8..15 (d2,d3)
            #pragma unroll
            for (int nt = 0; nt < 8; ++nt) {
                int c = nt * 8 + qc;
                float2 gv = *(const float2*)&sLN_i[64 + c];
                float2 bv = *(const float2*)&sLN_i[128 + c];
                float r2 = fmaf((D[nt][2] - muB) * rsB, gv.x, bv.x);
                float r3 = fmaf((D[nt][3] - muB) * rsB, gv.y, bv.y);
                *(float2*)&Fsw[qr * 66 + c] = make_float2(r2, r3);
            }
            __syncwarp();
            if ((lane >> 3) == mt * 2 + 1) {
                #pragma unroll
                for (int q = 0; q < 32; ++q)
                    bb[q] = add2(bb[q], *(ull*)&Fsw[(lane & 7) * 66 + 2 * q]);
            }
            __syncwarp();
        }
    }

    // ===== epilogue: z-mean over 8-lane groups =====
    {
        int cell = p >> 3;
        int iy = cell & 127;
        int ix = cell >> 7;
        int cidx = iy * XD + ix;
        bool writer = (lane & 7) == 0;
        #pragma unroll
        for (int q = 0; q < 32; ++q) {
            float a, b; unpk(bb[q], a, b);
            #pragma unroll
            for (int o = 1; o < 8; o <<= 1) {
                a += __shfl_xor_sync(0xffffffffu, a, o);
                b += __shfl_xor_sync(0xffffffffu, b, o);
            }
            if (writer) {
                out[(2 * q)     * (XD * YD) + cidx] = a * 0.125f;
                out[(2 * q + 1) * (XD * YD) + cidx] = b * 0.125f;
            }
        }
    }
}

// ---------------------------------------------------------------------------
extern "C" void kernel_launch(void* const* d_in, const int* in_sizes, int n_in,
                              void* d_out, int out_size) {
    const float* Tv     = (const float*)d_in[0];
    const float* intr   = (const float*)d_in[1];
    const float* img    = (const float*)d_in[2];
    const float* bev_in = (const float*)d_in[3];
    const float* W_off  = (const float*)d_in[4];
    const float* b_off  = (const float*)d_in[5];
    const float* s_off  = (const float*)d_in[6];
    const float* W_w    = (const float*)d_in[7];
    const float* b_w    = (const float*)d_in[8];
    const float* W_l    = (const float*)d_in[9];
    const float* b_l    = (const float*)d_in[10];
    const float* ln_g   = (const float*)d_in[11];
    const float* ln_b   = (const float*)d_in[12];
    float* out = (float*)d_out;

    cudaFuncSetAttribute(bev_kernel, cudaFuncAttributeMaxDynamicSharedMemorySize, SM_TOTAL);

    transpose_img_kernel<<<HW / 32, 256>>>(img);
    bev_kernel<<<NPTS / 256, 256, SM_TOTAL>>>(Tv, intr, bev_in,
                                              W_off, b_off, s_off, W_w, b_w,
                                              W_l, b_l, ln_g, ln_b, out);
}

// round 8
// speedup vs baseline: 1.3197x; 1.0017x over previous
#include <cuda_runtime.h>
#include <cuda_fp16.h>
#include <cstdint>

#define XD 128
#define YD 128
#define ZD 8
#define ED 64
#define NITER 3
#define FHD 96
#define FWD 320
#define NPTS (XD*YD*ZD)
#define HW (FHD*FWD)

typedef unsigned long long ull;

__device__ float g_imgT[HW * ED];   // (H,W,C) fp32 image, 7.9 MB

__device__ __forceinline__ ull pk2(float x, float y) {
    ull r; asm("mov.b64 %0,{%1,%2};" : "=l"(r) : "f"(x), "f"(y)); return r;
}
__device__ __forceinline__ ull splat(float x) { return pk2(x, x); }
__device__ __forceinline__ void unpk(ull v, float& x, float& y) {
    asm("mov.b64 {%0,%1},%2;" : "=f"(x), "=f"(y) : "l"(v));
}
__device__ __forceinline__ ull fma2(ull a, ull b, ull c) {
    ull d; asm("fma.rn.f32x2 %0,%1,%2,%3;" : "=l"(d) : "l"(a), "l"(b), "l"(c)); return d;
}
__device__ __forceinline__ ull add2(ull a, ull b) {
    ull d; asm("add.rn.f32x2 %0,%1,%2;" : "=l"(d) : "l"(a), "l"(b)); return d;
}
__device__ __forceinline__ uint32_t smem_u32(const void* p) {
    uint32_t a; asm("{ .reg .u64 t; cvta.to.shared.u64 t, %1; cvt.u32.u64 %0, t; }" : "=r"(a) : "l"(p));
    return a;
}

#define SWZ(off) ((off) ^ (((off) >> 3) & 0x70))

__device__ __forceinline__ void ldsm_x4(uint32_t& r0, uint32_t& r1, uint32_t& r2, uint32_t& r3,
                                        uint32_t addr) {
    asm volatile("ldmatrix.sync.aligned.m8n8.x4.shared.b16 {%0,%1,%2,%3}, [%4];"
                 : "=r"(r0), "=r"(r1), "=r"(r2), "=r"(r3) : "r"(addr));
}
__device__ __forceinline__ void ldsm_x4t(uint32_t& r0, uint32_t& r1, uint32_t& r2, uint32_t& r3,
                                         uint32_t addr) {
    asm volatile("ldmatrix.sync.aligned.m8n8.x4.trans.shared.b16 {%0,%1,%2,%3}, [%4];"
                 : "=r"(r0), "=r"(r1), "=r"(r2), "=r"(r3) : "r"(addr));
}
__device__ __forceinline__ void mma16816(float& d0, float& d1, float& d2, float& d3,
                                         uint32_t a0, uint32_t a1, uint32_t a2, uint32_t a3,
                                         uint32_t b0, uint32_t b1) {
    asm volatile("mma.sync.aligned.m16n8k16.row.col.f32.f16.f16.f32 "
                 "{%0,%1,%2,%3}, {%4,%5,%6,%7}, {%8,%9}, {%0,%1,%2,%3};"
                 : "+f"(d0), "+f"(d1), "+f"(d2), "+f"(d3)
                 : "r"(a0), "r"(a1), "r"(a2), "r"(a3), "r"(b0), "r"(b1));
}

// smem byte layout (85760 B total -> 2 CTAs/SM leaves ~56KB L1D for image)
// SM_AS region doubles as the per-warp gather table (disjoint lifetimes):
//   G1 writes table rows [pt][6 float4, SWZ] -> G2 reads -> A-tile overwrites.
#define SM_AS    0        // 8 warps x 4096B: gather table / fp16 A tile
#define SM_WB    32768    // 3 x 8192B fp16 W_l tiles (rows e, SW128)
#define SM_WD    57344    // 3 x 768 floats packed dot weights
#define SM_LN    66560    // 3 x 192 floats: b_l | ln_g | ln_b
#define SM_FS    68864    // 8 warps x 528 floats transpose buffer [8][66]
#define SM_TOTAL 85760

// ---------------------------------------------------------------------------
__global__ __launch_bounds__(256) void transpose_img_kernel(const float* __restrict__ img) {
    __shared__ float tile[32][65];
    const int r0 = blockIdx.x * 32;
    const int t  = threadIdx.x;
    const int tx = t & 31, ty = t >> 5;
    #pragma unroll
    for (int k = 0; k < 8; ++k) {
        int c = k * 8 + ty;
        tile[tx][c] = img[c * HW + r0 + tx];
    }
    __syncthreads();
    #pragma unroll
    for (int k = 0; k < 8; ++k) {
        int row = k * 4 + (t >> 6);
        int c   = t & 63;
        g_imgT[(r0 + row) * ED + c] = tile[row][c];
    }
}

// ---------------------------------------------------------------------------
__global__ __launch_bounds__(256, 2) void bev_kernel(
    const float* __restrict__ Tv,     const float* __restrict__ intr,
    const float* __restrict__ bev_in,
    const float* __restrict__ W_off,  const float* __restrict__ b_off,
    const float* __restrict__ s_off,  const float* __restrict__ W_w,
    const float* __restrict__ b_w,
    const float* __restrict__ W_l,    const float* __restrict__ b_l,
    const float* __restrict__ ln_g,   const float* __restrict__ ln_b,
    float* __restrict__ out)
{
    extern __shared__ char smem[];
    const uint32_t smb = smem_u32(smem);
    float* sWd = (float*)(smem + SM_WD);
    float* sLN = (float*)(smem + SM_LN);
    const int t    = threadIdx.x;
    const int warp = t >> 5;
    const int lane = t & 31;
    char* tw   = smem + SM_AS + warp * 4096;            // table / A tile region
    float* Fsw = (float*)(smem + SM_FS) + warp * 528;   // [8][66]
    const uint32_t asw = smb + SM_AS + warp * 4096;

    const int p = blockIdx.x * 256 + t;

    // ---- stage W_l as fp16 SW128 tiles (rows e, 128B rows) ----
    for (int idx = t; idx < NITER * 4096; idx += 256) {
        int i = idx >> 12;
        int r = idx & 4095;
        int e = r >> 6, c = r & 63;
        *(__half*)(smem + SM_WB + i * 8192 + SWZ((uint32_t)(e * 128 + c * 2))) =
            __float2half(W_l[idx]);
    }
    // ---- stage packed dot weights ----
    #pragma unroll
    for (int u = 0; u < 9; ++u) {
        int idx = t + u * 256;
        int i = idx / 768;
        int r = idx - i * 768;
        int e = r / 12, j = r - e * 12;
        float v = 0.0f;
        if (j < 6)      v = W_off[i * 384 + e * 6 + j];
        else if (j < 9) v = W_w[i * 192 + e * 3 + (j - 6)];
        sWd[idx] = v;
    }
    // ---- stage LN params: [i][ b_l(64) | ln_g(64) | ln_b(64) ] ----
    for (int idx = t; idx < NITER * 192; idx += 256) {
        int i = idx / 192;
        int r = idx - i * 192;
        int j = r >> 6, e = r & 63;
        float v = (j == 0) ? b_l[i * ED + e] : (j == 1) ? ln_g[i * ED + e] : ln_b[i * ED + e];
        sLN[idx] = v;
    }

    // ---- projected base coords ----
    float pxb, pyb;
    {
        int iz = p & 7;
        int ixy = p >> 3;
        int iy = ixy & 127;
        int ix = ixy >> 7;
        float gx = (float)ix * 0.8f;
        float gy = 51.2f - (float)iy * 0.8f;
        float gz = (float)iz * 0.5f - 2.5f;
        float q0 = Tv[0]*gx + Tv[1]*gy + Tv[2]*gz  + Tv[3];
        float q1 = Tv[4]*gx + Tv[5]*gy + Tv[6]*gz  + Tv[7];
        float q2 = Tv[8]*gx + Tv[9]*gy + Tv[10]*gz + Tv[11];
        float r0 = intr[0]*q0 + intr[1]*q1 + intr[2]*q2;
        float r1 = intr[3]*q0 + intr[4]*q1 + intr[5]*q2;
        float r2 = intr[6]*q0 + intr[7]*q1 + intr[8]*q2;
        float invz = 1.0f / r2;
        float cx = r0 * invz * (1.0f / 640.0f) - 1.0f;
        float cy = r1 * invz * (1.0f / 192.0f) - 1.0f;
        pxb = cx * 160.0f + 159.5f;
        pyb = cy * 48.0f  + 47.5f;
    }

    // ---- load B state into registers (smem transpose, 8-row groups) ----
    ull bb[32];
    const int pwarp0 = blockIdx.x * 256 + warp * 32;
    #pragma unroll
    for (int g = 0; g < 4; ++g) {
        #pragma unroll
        for (int q = 0; q < 8; ++q) {
            int pt = pwarp0 + g * 8 + q;
            ull v = *((const ull*)(bev_in + (size_t)pt * ED) + lane);
            *(ull*)&Fsw[q * 66 + 2 * lane] = v;
        }
        __syncwarp();
        if ((lane >> 3) == g) {
            #pragma unroll
            for (int q = 0; q < 32; ++q)
                bb[q] = *(ull*)&Fsw[(lane & 7) * 66 + 2 * q];
        }
        __syncwarp();
    }

    __syncthreads();   // weights staged

    for (int i = 0; i < NITER; ++i) {
        const float* sWd_i = sWd + i * 768;
        const float* sLN_i = sLN + i * 192;
        const uint32_t wb_i = smb + SM_WB + i * 8192;

        // ===== dots: 10 logits, broadcast weight rows =====
        float d[10];
        {
            ull acc[5] = {0, 0, 0, 0, 0};
            #pragma unroll
            for (int ep = 0; ep < 32; ++ep) {
                float be0, be1; unpk(bb[ep], be0, be1);
                ull bs0 = splat(be0), bs1 = splat(be1);
                const ulonglong2* w0 = (const ulonglong2*)&sWd_i[(2 * ep) * 12];
                const ulonglong2* w1 = (const ulonglong2*)&sWd_i[(2 * ep + 1) * 12];
                ulonglong2 wa = w0[0], wb = w0[1], wc = w0[2];
                acc[0] = fma2(bs0, wa.x, acc[0]); acc[1] = fma2(bs0, wa.y, acc[1]);
                acc[2] = fma2(bs0, wb.x, acc[2]); acc[3] = fma2(bs0, wb.y, acc[3]);
                acc[4] = fma2(bs0, wc.x, acc[4]);
                wa = w1[0]; wb = w1[1]; wc = w1[2];
                acc[0] = fma2(bs1, wa.x, acc[0]); acc[1] = fma2(bs1, wa.y, acc[1]);
                acc[2] = fma2(bs1, wb.x, acc[2]); acc[3] = fma2(bs1, wb.y, acc[3]);
                acc[4] = fma2(bs1, wc.x, acc[4]);
            }
            #pragma unroll
            for (int q = 0; q < 5; ++q) unpk(acc[q], d[2 * q], d[2 * q + 1]);
        }

        // ===== G1: offsets/softmax -> gather table (SWZ rows in AS region) =====
        {
            const float sc = __ldg(s_off + i);
            float off[6];
            #pragma unroll
            for (int j = 0; j < 6; ++j) off[j] = (d[j] + __ldg(b_off + i * 6 + j)) * sc;
            float l0 = d[6] + __ldg(b_w + i * 3 + 0);
            float l1 = d[7] + __ldg(b_w + i * 3 + 1);
            float l2 = d[8] + __ldg(b_w + i * 3 + 2);
            float mx = fmaxf(l0, fmaxf(l1, l2));
            float e0 = __expf(l0 - mx), e1 = __expf(l1 - mx), e2 = __expf(l2 - mx);
            float inv = 1.0f / (e0 + e1 + e2);
            float wk[3] = {e0 * inv, e1 * inv, e2 * inv};
            #pragma unroll
            for (int k = 0; k < 3; ++k) {
                float px = fmaf(off[2 * k],     160.0f, pxb);
                float py = fmaf(off[2 * k + 1],  48.0f, pyb);
                float fx = floorf(px), fy = floorf(py);
                int x0 = (int)fx, y0 = (int)fy;
                float wx1 = px - fx, wy1 = py - fy;
                float wx0 = 1.0f - wx1, wy0 = 1.0f - wy1;
                bool vx0 = (unsigned)x0 < (unsigned)FWD, vx1 = (unsigned)(x0 + 1) < (unsigned)FWD;
                bool vy0 = (unsigned)y0 < (unsigned)FHD, vy1 = (unsigned)(y0 + 1) < (unsigned)FHD;
                int xc0 = min(max(x0, 0), FWD - 1), xc1 = min(max(x0 + 1, 0), FWD - 1);
                int yc0 = min(max(y0, 0), FHD - 1), yc1 = min(max(y0 + 1, 0), FHD - 1);
                int rA = yc0 * FWD, rB = yc1 * FWD;
                float W = wk[k];
                float w00 = (vx0 && vy0) ? W * wx0 * wy0 : 0.0f;
                float w01 = (vx1 && vy0) ? W * wx1 * wy0 : 0.0f;
                float w10 = (vx0 && vy1) ? W * wx0 * wy1 : 0.0f;
                float w11 = (vx1 && vy1) ? W * wx1 * wy1 : 0.0f;
                *(float4*)(tw + SWZ((uint32_t)(lane * 128 + k * 32))) = make_float4(
                    __int_as_float((rA + xc0) << 6), __int_as_float((rA + xc1) << 6),
                    __int_as_float((rB + xc0) << 6), __int_as_float((rB + xc1) << 6));
                *(float4*)(tw + SWZ((uint32_t)(lane * 128 + k * 32 + 16))) =
                    make_float4(w00, w01, w10, w11);
            }
        }
        __syncwarp();

        // ===== G2: warp-per-point gather (fp32 image), fold into bb =====
        #pragma unroll 1
        for (int g = 0; g < 4; ++g) {
            #pragma unroll 4
            for (int q = 0; q < 8; ++q) {
                const int pt = g * 8 + q;
                float a0 = 0.0f, a1 = 0.0f;
                #pragma unroll
                for (int k = 0; k < 3; ++k) {
                    float4 A  = *(const float4*)(tw + SWZ((uint32_t)(pt * 128 + k * 32)));
                    float4 Wt = *(const float4*)(tw + SWZ((uint32_t)(pt * 128 + k * 32 + 16)));
                    float2 v;
                    v = *(const float2*)(g_imgT + __float_as_int(A.x) + 2 * lane);
                    a0 = fmaf(Wt.x, v.x, a0); a1 = fmaf(Wt.x, v.y, a1);
                    v = *(const float2*)(g_imgT + __float_as_int(A.y) + 2 * lane);
                    a0 = fmaf(Wt.y, v.x, a0); a1 = fmaf(Wt.y, v.y, a1);
                    v = *(const float2*)(g_imgT + __float_as_int(A.z) + 2 * lane);
                    a0 = fmaf(Wt.z, v.x, a0); a1 = fmaf(Wt.z, v.y, a1);
                    v = *(const float2*)(g_imgT + __float_as_int(A.w) + 2 * lane);
                    a0 = fmaf(Wt.w, v.x, a0); a1 = fmaf(Wt.w, v.y, a1);
                }
                *(ull*)&Fsw[q * 66 + 2 * lane] = pk2(a0, a1);
            }
            __syncwarp();
            if ((lane >> 3) == g) {
                #pragma unroll
                for (int q = 0; q < 32; ++q)
                    bb[q] = add2(bb[q], *(ull*)&Fsw[(lane & 7) * 66 + 2 * q]);
            }
            __syncwarp();
        }

        // ===== write own row of A tile (fp16, SW128) — overwrites table =====
        {
            uint32_t av[32];
            #pragma unroll
            for (int q = 0; q < 32; ++q) {
                float a, b; unpk(bb[q], a, b);
                __half2 hh = __floats2half2_rn(a, b);
                av[q] = *(uint32_t*)&hh;
            }
            __syncwarp();   // all table reads complete before overwrite
            #pragma unroll
            for (int cb = 0; cb < 8; ++cb) {
                uint32_t off = SWZ((uint32_t)(lane * 128 + cb * 16));
                *(uint4*)(tw + off) =
                    make_uint4(av[4*cb], av[4*cb+1], av[4*cb+2], av[4*cb+3]);
            }
        }
        __syncwarp();

        // ===== matvec via mma.sync, two m16 halves =====
        const int qr = lane >> 2;        // quad row 0..7
        const int qc = (lane & 3) * 2;   // col pair base within n8 tile
        #pragma unroll
        for (int mt = 0; mt < 2; ++mt) {
            float D[8][4];
            #pragma unroll
            for (int nt = 0; nt < 8; ++nt) {
                float2 bv = *(const float2*)&sLN_i[nt * 8 + qc];
                D[nt][0] = bv.x; D[nt][1] = bv.y;
                D[nt][2] = bv.x; D[nt][3] = bv.y;
            }
            const uint32_t arow = (uint32_t)(mt * 16 + (lane & 15));
            const uint32_t koff8 = (uint32_t)(((lane >> 4) & 1) << 3);
            #pragma unroll
            for (int kt = 0; kt < 4; ++kt) {
                uint32_t a0, a1, a2, a3;
                ldsm_x4(a0, a1, a2, a3,
                        asw + SWZ(arow * 128 + (kt * 16 + koff8) * 2));
                const uint32_t brow = (uint32_t)(kt * 16 + (lane & 15));
                #pragma unroll
                for (int np = 0; np < 4; ++np) {
                    uint32_t b0, b1, b2, b3;
                    ldsm_x4t(b0, b1, b2, b3,
                             wb_i + SWZ(brow * 128 + (np * 16 + koff8) * 2));
                    mma16816(D[2*np][0],   D[2*np][1],   D[2*np][2],   D[2*np][3],
                             a0, a1, a2, a3, b0, b1);
                    mma16816(D[2*np+1][0], D[2*np+1][1], D[2*np+1][2], D[2*np+1][3],
                             a0, a1, a2, a3, b2, b3);
                }
            }
            float s1a = 0.f, s2a = 0.f, s1b = 0.f, s2b = 0.f;
            #pragma unroll
            for (int nt = 0; nt < 8; ++nt) {
                s1a += D[nt][0] + D[nt][1];
                s2a = fmaf(D[nt][0], D[nt][0], s2a); s2a = fmaf(D[nt][1], D[nt][1], s2a);
                s1b += D[nt][2] + D[nt][3];
                s2b = fmaf(D[nt][2], D[nt][2], s2b); s2b = fmaf(D[nt][3], D[nt][3], s2b);
            }
            #pragma unroll
            for (int o = 1; o < 4; o <<= 1) {
                s1a += __shfl_xor_sync(0xffffffffu, s1a, o);
                s2a += __shfl_xor_sync(0xffffffffu, s2a, o);
                s1b += __shfl_xor_sync(0xffffffffu, s1b, o);
                s2b += __shfl_xor_sync(0xffffffffu, s2b, o);
            }
            float muA = s1a * (1.0f / ED);
            float rsA = rsqrtf(s2a * (1.0f / ED) - muA * muA + 1e-5f);
            float muB = s1b * (1.0f / ED);
            float rsB = rsqrtf(s2b * (1.0f / ED) - muB * muB + 1e-5f);

            #pragma unroll
            for (int nt = 0; nt < 8; ++nt) {
                int c = nt * 8 + qc;
                float2 gv = *(const float2*)&sLN_i[64 + c];
                float2 bv = *(const float2*)&sLN_i[128 + c];
                float r0 = fmaf((D[nt][0] - muA) * rsA, gv.x, bv.x);
                float r1 = fmaf((D[nt][1] - muA) * rsA, gv.y, bv.y);
                *(float2*)&Fsw[qr * 66 + c] = make_float2(r0, r1);
            }
            __syncwarp();
            if ((lane >> 3) == mt * 2) {
                #pragma unroll
                for (int q = 0; q < 32; ++q)
                    bb[q] = add2(bb[q], *(ull*)&Fsw[(lane & 7) * 66 + 2 * q]);
            }
            __syncwarp();
            #pragma unroll
            for (int nt = 0; nt < 8; ++nt) {
                int c = nt * 8 + qc;
                float2 gv = *(const float2*)&sLN_i[64 + c];
                float2 bv = *(const float2*)&sLN_i[128 + c];
                float r2 = fmaf((D[nt][2] - muB) * rsB, gv.x, bv.x);
                float r3 = fmaf((D[nt][3] - muB) * rsB, gv.y, bv.y);
                *(float2*)&Fsw[qr * 66 + c] = make_float2(r2, r3);
            }
            __syncwarp();
            if ((lane >> 3) == mt * 2 + 1) {
                #pragma unroll
                for (int q = 0; q < 32; ++q)
                    bb[q] = add2(bb[q], *(ull*)&Fsw[(lane & 7) * 66 + 2 * q]);
            }
            __syncwarp();
        }
    }

    // ===== epilogue: z-mean over 8-lane groups =====
    {
        int cell = p >> 3;
        int iy = cell & 127;
        int ix = cell >> 7;
        int cidx = iy * XD + ix;
        bool writer = (lane & 7) == 0;
        #pragma unroll
        for (int q = 0; q < 32; ++q) {
            float a, b; unpk(bb[q], a, b);
            #pragma unroll
            for (int o = 1; o < 8; o <<= 1) {
                a += __shfl_xor_sync(0xffffffffu, a, o);
                b += __shfl_xor_sync(0xffffffffu, b, o);
            }
            if (writer) {
                out[(2 * q)     * (XD * YD) + cidx] = a * 0.125f;
                out[(2 * q + 1) * (XD * YD) + cidx] = b * 0.125f;
            }
        }
    }
}

// ---------------------------------------------------------------------------
extern "C" void kernel_launch(void* const* d_in, const int* in_sizes, int n_in,
                              void* d_out, int out_size) {
    const float* Tv     = (const float*)d_in[0];
    const float* intr   = (const float*)d_in[1];
    const float* img    = (const float*)d_in[2];
    const float* bev_in = (const float*)d_in[3];
    const float* W_off  = (const float*)d_in[4];
    const float* b_off  = (const float*)d_in[5];
    const float* s_off  = (const float*)d_in[6];
    const float* W_w    = (const float*)d_in[7];
    const float* b_w    = (const float*)d_in[8];
    const float* W_l    = (const float*)d_in[9];
    const float* b_l    = (const float*)d_in[10];
    const float* ln_g   = (const float*)d_in[11];
    const float* ln_b   = (const float*)d_in[12];
    float* out = (float*)d_out;

    cudaFuncSetAttribute(bev_kernel, cudaFuncAttributeMaxDynamicSharedMemorySize, SM_TOTAL);

    transpose_img_kernel<<<HW / 32, 256>>>(img);
    bev_kernel<<<NPTS / 256, 256, SM_TOTAL>>>(Tv, intr, bev_in,
                                              W_off, b_off, s_off, W_w, b_w,
                                              W_l, b_l, ln_g, ln_b, out);
}